// round 11
// baseline (speedup 1.0000x reference)
#include <cuda_runtime.h>
#include <cstdint>

#define HS    128
#define KITER 40
#define NIMG  256
#define RPC   16            // rows per CTA
#define NCTA  8             // cluster size (8 * 16 = 128 rows)
#define S     132           // padded row stride (floats)
#define VROWS 18            // RPC + 2 halo rows
#define NTHR  256

#define MB_F       8                   // 4 mbarriers (u64) = 32 B
#define CR_F       (5*8*NTHR*2)        // cr: 20480 floats (80 KB)
#define VBUF_F     (VROWS*S)           // 2376 floats
#define EXP_F      (4*S)               // exp_top[2 par] + exp_bot[2 par]
#define W_F        100                 // 5 cp * 10 u64-slots * 2 floats
#define SM_FLOATS  (MB_F + CR_F + 2*VBUF_F + EXP_F + 2*W_F + 48)
#define SMEM_BYTES (SM_FLOATS*4)

__device__ float g_eff[19];   // collapsed h->r conv weights (18) + bias

// ---------------- prep: collapse h_w/h_b/r_w into 2x3x3 eff conv ----------------
__global__ void vin_prep(const float* __restrict__ h_w,
                         const float* __restrict__ h_b,
                         const float* __restrict__ r_w) {
    int t = threadIdx.x;
    if (t < 18) {
        float s = 0.f;
        for (int c = 0; c < 150; ++c) s += r_w[c] * h_w[c*18 + t];
        g_eff[t] = s;
    } else if (t == 18) {
        float s = 0.f;
        for (int c = 0; c < 150; ++c) s += r_w[c] * h_b[c];
        g_eff[18] = s;
    }
}

// ---------------- f32x2 / PTX helpers ----------------
__device__ __forceinline__ unsigned long long dup2(float x) {
    unsigned long long d;
    asm("mov.b64 %0, {%1, %1};" : "=l"(d) : "f"(x));
    return d;
}
__device__ __forceinline__ unsigned long long fma2(unsigned long long a,
                                                   unsigned long long b,
                                                   unsigned long long c) {
    unsigned long long d;
    asm("fma.rn.f32x2 %0, %1, %2, %3;" : "=l"(d) : "l"(a), "l"(b), "l"(c));
    return d;
}
__device__ __forceinline__ unsigned long long mul2(unsigned long long a,
                                                   unsigned long long b) {
    unsigned long long d;
    asm("mul.rn.f32x2 %0, %1, %2;" : "=l"(d) : "l"(a), "l"(b));
    return d;
}
__device__ __forceinline__ float2 u2f(unsigned long long u) {
    float2 f;
    asm("mov.b64 {%0, %1}, %2;" : "=f"(f.x), "=f"(f.y) : "l"(u));
    return f;
}
__device__ __forceinline__ uint32_t smem_u32(const void* p) {
    uint32_t a;
    asm("{ .reg .u64 t; cvta.to.shared.u64 t, %1; cvt.u32.u64 %0, t; }"
        : "=r"(a) : "l"(p));
    return a;
}
__device__ __forceinline__ uint32_t mapa_rank(uint32_t addr, uint32_t rank) {
    uint32_t r;
    asm("mapa.shared::cluster.u32 %0, %1, %2;" : "=r"(r) : "r"(addr), "r"(rank));
    return r;
}
__device__ __forceinline__ float dsmem_ld(const float* p, uint32_t rank) {
    uint32_t a = smem_u32(p), r;
    asm("mapa.shared::cluster.u32 %0, %1, %2;" : "=r"(r) : "r"(a), "r"(rank));
    float v;
    asm volatile("ld.shared::cluster.f32 %0, [%1];" : "=f"(v) : "r"(r));
    return v;
}
__device__ __forceinline__ void mbar_init(uint32_t addr, uint32_t cnt) {
    asm volatile("mbarrier.init.shared.b64 [%0], %1;" :: "r"(addr), "r"(cnt) : "memory");
}
__device__ __forceinline__ void mbar_arrive_remote(uint32_t local_addr, uint32_t rank) {
    uint32_t raddr = mapa_rank(local_addr, rank);
    asm volatile("mbarrier.arrive.release.cluster.shared::cluster.b64 _, [%0];"
                 :: "r"(raddr) : "memory");
}
__device__ __forceinline__ void mbar_wait(uint32_t addr, uint32_t parity) {
    uint32_t done;
    do {
        asm volatile(
            "{ .reg .pred p;\n"
            "  mbarrier.try_wait.parity.acquire.cluster.shared::cta.b64 p, [%1], %2;\n"
            "  selp.b32 %0, 1, 0, p; }\n"
            : "=r"(done) : "r"(addr), "r"(parity) : "memory");
    } while (!done);
}
// per-warp-pair iteration flags (CTA-local producer/consumer counters)
__device__ __forceinline__ void flag_set(uint32_t addr, uint32_t v) {
    asm volatile("st.release.cta.shared::cta.u32 [%0], %1;" :: "r"(addr), "r"(v) : "memory");
}
__device__ __forceinline__ void flag_wait_ge(uint32_t addr, uint32_t v) {
    uint32_t x;
    do {
        asm volatile("ld.acquire.cta.shared::cta.u32 %0, [%1];" : "=r"(x) : "r"(addr) : "memory");
    } while ((int)x < (int)v);
}
#define CLUSTER_SYNC() do { \
    asm volatile("barrier.cluster.arrive.aligned;" ::: "memory"); \
    asm volatile("barrier.cluster.wait.aligned;"   ::: "memory"); \
} while (0)

extern __shared__ float smem[];

// ---------------- main: 8-CTA cluster, p2p mbarriers + per-warp flag desync ----------------
__global__ void __launch_bounds__(NTHR, 2) __cluster_dims__(NCTA, 1, 1)
vin_main(const float* __restrict__ input_view,
         const int*   __restrict__ coords,
         const float* __restrict__ q_w,
         const float* __restrict__ w,
         const float* __restrict__ fc_w,
         float*       __restrict__ out)
{
    ulonglong2* crp = (ulonglong2*)(smem + MB_F);
    float* buf0 = smem + MB_F + CR_F;
    float* buf1 = buf0 + VBUF_F;
    float* exp_ = buf1 + VBUF_F;   // exp_top[par]=exp_+par*S ; exp_bot[par]=exp_+(2+par)*S
    float* wq_s = exp_ + EXP_F;
    float* wv_s = wq_s + W_F;
    float* qfin = wv_s + W_F;
    float* flags = qfin + 16;      // rd_ct[0..7], wr_ct[0..7] as u32

    const int tid  = threadIdx.x;
    const int wid  = tid >> 5;
    const int lid  = tid & 31;
    const int img  = blockIdx.x >> 3;
    const int rank = blockIdx.x & 7;
    const int r0   = rank * RPC;

    const uint32_t mb_base = smem_u32(smem);
    const uint32_t fl_base = smem_u32(flags);
    const uint32_t rd_ct   = fl_base;        // 8 u32
    const uint32_t wr_ct   = fl_base + 32;   // 8 u32

    // zero v buffers + exports + weights + qfin + flags
    for (int i = tid; i < 2*VBUF_F + EXP_F + 2*W_F + 48; i += NTHR) buf0[i] = 0.f;
    if (tid == 0) {
        mbar_init(mb_base + 0,  1);   // top, slot 0
        mbar_init(mb_base + 8,  1);   // top, slot 1
        mbar_init(mb_base + 16, 1);   // bot, slot 0
        mbar_init(mb_base + 24, 1);   // bot, slot 1
    }
    __syncthreads();
    if (tid < 90) {
        int c = tid/9, t9 = tid%9, cp = c>>1, half = c&1;
        wq_s[(cp*10 + t9)*2 + half] = q_w[c*9 + t9];
        wv_s[(cp*10 + t9)*2 + half] = w  [c*9 + t9];
    }
    __syncthreads();
    CLUSTER_SYNC();   // mbar init visible cluster-wide before any remote arrive

    // ---- stage A: r rows [r0-1, r0+16] into buf1 (temp) ----
    {
        float e[19];
        #pragma unroll
        for (int i = 0; i < 19; ++i) e[i] = g_eff[i];
        const float* inb = input_view + (size_t)img * 2 * HS * HS;
        for (int idx = tid; idx < VROWS*HS; idx += NTHR) {
            int j = idx >> 7, x = idx & 127;
            int gy = r0 - 1 + j;
            float acc = 0.f;
            if ((unsigned)gy < (unsigned)HS) {
                acc = e[18];
                #pragma unroll
                for (int ch = 0; ch < 2; ++ch) {
                    const float* ip = inb + ch*HS*HS;
                    #pragma unroll
                    for (int ky = 0; ky < 3; ++ky) {
                        int yy = gy + ky - 1;
                        if ((unsigned)yy < (unsigned)HS) {
                            #pragma unroll
                            for (int kx = 0; kx < 3; ++kx) {
                                int xx = x + kx - 1;
                                if ((unsigned)xx < (unsigned)HS)
                                    acc += ip[yy*HS + xx] * e[ch*9 + ky*3 + kx];
                            }
                        }
                    }
                }
            }
            buf1[j*S + x + 1] = acc;
        }
    }
    __syncthreads();

    const int y  = tid >> 4;          // owned row 0..15
    const int x0 = (tid & 15) << 3;   // 0..120

    // ---- stage B: cr = conv(r, q_w), paired ulonglong2 layout ----
    {
        unsigned long long rd[3][10];
        #pragma unroll
        for (int rr = 0; rr < 3; ++rr) {
            const float4* p = (const float4*)(buf1 + (y+rr)*S + x0);
            float4 a = p[0], b4 = p[1], c4 = p[2];
            rd[rr][0]=dup2(a.x);  rd[rr][1]=dup2(a.y);  rd[rr][2]=dup2(a.z);  rd[rr][3]=dup2(a.w);
            rd[rr][4]=dup2(b4.x); rd[rr][5]=dup2(b4.y); rd[rr][6]=dup2(b4.z); rd[rr][7]=dup2(b4.w);
            rd[rr][8]=dup2(c4.x); rd[rr][9]=dup2(c4.y);
        }
        #pragma unroll
        for (int cp = 0; cp < 5; ++cp) {
            unsigned long long W[9];
            #pragma unroll
            for (int t9 = 0; t9 < 9; ++t9)
                W[t9] = *(const unsigned long long*)(wq_s + (cp*10 + t9)*2);
            unsigned long long acc[8];
            #pragma unroll
            for (int px = 0; px < 8; ++px) {
                unsigned long long a = mul2(rd[0][px], W[0]);
                a = fma2(rd[0][px+1], W[1], a);
                a = fma2(rd[0][px+2], W[2], a);
                a = fma2(rd[1][px],   W[3], a);
                a = fma2(rd[1][px+1], W[4], a);
                a = fma2(rd[1][px+2], W[5], a);
                a = fma2(rd[2][px],   W[6], a);
                a = fma2(rd[2][px+1], W[7], a);
                a = fma2(rd[2][px+2], W[8], a);
                acc[px] = a;
            }
            #pragma unroll
            for (int pp = 0; pp < 4; ++pp)
                crp[(pp*5 + cp)*NTHR + tid] = make_ulonglong2(acc[2*pp], acc[2*pp+1]);
        }
    }
    __syncthreads();
    for (int i = tid; i < VBUF_F; i += NTHR) buf1[i] = 0.f;
    __syncthreads();

    // ---- 40 sweeps; per-warp flag handshake (skew-tolerant), no CTA barrier ----
    #pragma unroll 1
    for (int it = 0; it < KITER; ++it) {
        const float* vc = (it & 1) ? buf1 : buf0;
        float*       vn = (it & 1) ? buf0 : buf1;
        const int b_out = it & 1;

        if (it > 0) {
            // interior deps: neighbors must have finished WRITING iteration it-1
            if (wid > 0) flag_wait_ge(wr_ct + 4*(wid-1), (uint32_t)it);
            if (wid < 7) flag_wait_ge(wr_ct + 4*(wid+1), (uint32_t)it);
            // edge warps: inter-CTA halo (cluster mbar + pull)
            const int b_in = (it - 1) & 1;
            const uint32_t par = (uint32_t)(((it - 1) >> 1) & 1);
            if (wid == 0) {
                if (rank > 0) {
                    mbar_wait(mb_base + b_in*8, par);
                    #pragma unroll
                    for (int j = 0; j < 4; ++j) {
                        int xx = lid*4 + j;
                        ((float*)vc)[0*S + 1 + xx] =
                            dsmem_ld(exp_ + (2 + b_in)*S + 1 + xx, rank - 1);
                    }
                }
                __syncwarp();
            } else if (wid == 7) {
                if (rank < NCTA-1) {
                    mbar_wait(mb_base + 16 + b_in*8, par);
                    #pragma unroll
                    for (int j = 0; j < 4; ++j) {
                        int xx = lid*4 + j;
                        ((float*)vc)[(RPC+1)*S + 1 + xx] =
                            dsmem_ld(exp_ + b_in*S + 1 + xx, rank + 1);
                    }
                }
                __syncwarp();
            }
        }

        unsigned long long vd[3][10];
        #pragma unroll
        for (int rr = 0; rr < 3; ++rr) {
            const float4* p = (const float4*)(vc + (y+rr)*S + x0);
            float4 a = p[0], b4 = p[1], c4 = p[2];
            vd[rr][0]=dup2(a.x);  vd[rr][1]=dup2(a.y);  vd[rr][2]=dup2(a.z);  vd[rr][3]=dup2(a.w);
            vd[rr][4]=dup2(b4.x); vd[rr][5]=dup2(b4.y); vd[rr][6]=dup2(b4.z); vd[rr][7]=dup2(b4.w);
            vd[rr][8]=dup2(c4.x); vd[rr][9]=dup2(c4.y);
        }
        // all vc loads are consumed by the dup2 MOVs above -> safe to signal read-done
        __syncwarp();
        if (lid == 0) flag_set(rd_ct + 4*wid, (uint32_t)(it + 1));

        float vmx[8], vmy[8];
        #pragma unroll
        for (int cp = 0; cp < 5; ++cp) {
            const ulonglong2* wp = (const ulonglong2*)(wv_s + cp*20);
            ulonglong2 w01 = wp[0], w23 = wp[1], w45 = wp[2], w67 = wp[3];
            unsigned long long W8 = *(const unsigned long long*)(wv_s + cp*20 + 16);
            ulonglong2 c01 = crp[(0*5 + cp)*NTHR + tid];
            ulonglong2 c23 = crp[(1*5 + cp)*NTHR + tid];
            ulonglong2 c45 = crp[(2*5 + cp)*NTHR + tid];
            ulonglong2 c67 = crp[(3*5 + cp)*NTHR + tid];
            unsigned long long acc[8] = {c01.x, c01.y, c23.x, c23.y,
                                         c45.x, c45.y, c67.x, c67.y};
            #pragma unroll
            for (int px = 0; px < 8; ++px) {
                unsigned long long a = acc[px];
                a = fma2(vd[0][px],   w01.x, a);
                a = fma2(vd[0][px+1], w01.y, a);
                a = fma2(vd[0][px+2], w23.x, a);
                a = fma2(vd[1][px],   w23.y, a);
                a = fma2(vd[1][px+1], w45.x, a);
                a = fma2(vd[1][px+2], w45.y, a);
                a = fma2(vd[2][px],   w67.x, a);
                a = fma2(vd[2][px+1], w67.y, a);
                a = fma2(vd[2][px+2], W8,    a);
                float2 aa = u2f(a);
                if (cp == 0) { vmx[px] = aa.x;                 vmy[px] = aa.y; }
                else         { vmx[px] = fmaxf(vmx[px], aa.x); vmy[px] = fmaxf(vmy[px], aa.y); }
            }
        }

        // before overwriting vn (same buffer neighbors read at it-1): wait their read-done
        if (it > 0) {
            if (wid > 0) flag_wait_ge(rd_ct + 4*(wid-1), (uint32_t)it);
            if (wid < 7) flag_wait_ge(rd_ct + 4*(wid+1), (uint32_t)it);
        }

        float* vo = vn + (y+1)*S + x0 + 1;
        float res[8];
        #pragma unroll
        for (int px = 0; px < 8; ++px) { res[px] = fmaxf(vmx[px], vmy[px]); vo[px] = res[px]; }

        // edge-row exports into parity slots
        if (y == 0) {
            if (rank > 0) {
                float* e = exp_ + b_out*S + x0 + 1;
                #pragma unroll
                for (int px = 0; px < 8; ++px) e[px] = res[px];
            }
        } else if (y == 15) {
            if (rank < NCTA-1) {
                float* e = exp_ + (2 + b_out)*S + x0 + 1;
                #pragma unroll
                for (int px = 0; px < 8; ++px) e[px] = res[px];
            }
        }

        __syncwarp();
        if (lid == 0) flag_set(wr_ct + 4*wid, (uint32_t)(it + 1));

        // edge warps: signal neighbor CTA (release-arrive after export)
        if (wid == 0) {
            if (lid == 0 && rank > 0)
                mbar_arrive_remote(mb_base + 16 + b_out*8, rank - 1);  // their mb_bot
        } else if (wid == 7) {
            if (lid == 0 && rank < NCTA-1)
                mbar_arrive_remote(mb_base + b_out*8, rank + 1);        // their mb_top
        }
    }

    // ---- refresh buf0 halo for readout (final v = buf0, exported at it=39) ----
    {
        const int b = (KITER - 1) & 1;                            // 1
        const uint32_t par = (uint32_t)(((KITER - 1) >> 1) & 1);  // 1
        if (wid == 0) {
            if (rank > 0) {
                mbar_wait(mb_base + b*8, par);
                #pragma unroll
                for (int j = 0; j < 4; ++j) {
                    int xx = lid*4 + j;
                    buf0[0*S + 1 + xx] = dsmem_ld(exp_ + (2 + b)*S + 1 + xx, rank - 1);
                }
            }
        } else if (wid == 7) {
            if (rank < NCTA-1) {
                mbar_wait(mb_base + 16 + b*8, par);
                #pragma unroll
                for (int j = 0; j < 4; ++j) {
                    int xx = lid*4 + j;
                    buf0[(RPC+1)*S + 1 + xx] = dsmem_ld(exp_ + b*S + 1 + xx, rank + 1);
                }
            }
        }
    }
    __syncthreads();

    // ---- readout ----
    const int sx = coords[img*4 + 0];
    const int sy = coords[img*4 + 1];
    if ((sx >> 4) == rank) {
        const float* vf = buf0;
        const int yl = sx & 15;
        if (tid < 10) {
            int tt = yl*16 + (sy >> 3), slot = sy & 7;
            int cp = tid >> 1, half = tid & 1;
            ulonglong2 ce = crp[((slot >> 1)*5 + cp)*NTHR + tt];
            float2 crv = u2f((slot & 1) ? ce.y : ce.x);
            float acc = half ? crv.y : crv.x;
            #pragma unroll
            for (int rr = 0; rr < 3; ++rr)
                #pragma unroll
                for (int cc = 0; cc < 3; ++cc)
                    acc += w[tid*9 + rr*3 + cc] * vf[(yl + rr)*S + sy + cc];
            qfin[tid] = acc;
        }
        __syncthreads();
        if (tid < 5) {
            float s = 0.f;
            #pragma unroll
            for (int c = 0; c < 10; ++c) s += qfin[c] * fc_w[tid*10 + c];
            out[img*5 + tid] = s;
        }
    }

    // no CTA may exit while a neighbor's remote op targeting it can be in flight
    CLUSTER_SYNC();
}

extern "C" void kernel_launch(void* const* d_in, const int* in_sizes, int n_in,
                              void* d_out, int out_size) {
    const float* input_view = (const float*)d_in[0];
    const int*   coords     = (const int*)  d_in[1];
    const float* h_w        = (const float*)d_in[2];
    const float* h_b        = (const float*)d_in[3];
    const float* r_w        = (const float*)d_in[4];
    const float* q_w        = (const float*)d_in[5];
    const float* w          = (const float*)d_in[6];
    const float* fc_w       = (const float*)d_in[7];
    float* out = (float*)d_out;

    (void)in_sizes; (void)n_in; (void)out_size;

    vin_prep<<<1, 32>>>(h_w, h_b, r_w);

    cudaFuncSetAttribute(vin_main, cudaFuncAttributeMaxDynamicSharedMemorySize, SMEM_BYTES);
    vin_main<<<NIMG*NCTA, NTHR, SMEM_BYTES>>>(input_view, coords, q_w, w, fc_w, out);
}

// round 12
// speedup vs baseline: 1.0515x; 1.0515x over previous
#include <cuda_runtime.h>
#include <cstdint>

#define HS    128
#define KITER 40
#define NIMG  256
#define RPC   16            // rows per CTA
#define NCTA  8             // cluster size (8 * 16 = 128 rows)
#define S     132           // padded row stride (floats)
#define VROWS 18            // RPC + 2 halo rows
#define NTHR  512           // 16 warps, 1 row per warp, 4 px per thread

#define MB_F       8                   // 4 mbarriers (u64) = 32 B
#define CR_F       20480               // cr: 2pp * 5cp * 512thr * ull2 = 80 KB
#define VBUF_F     (VROWS*S)           // 2376 floats
#define EXP_F      (4*S)               // exp_top[2 par] + exp_bot[2 par]
#define W_F        100                 // 5 cp * 10 u64-slots * 2 floats
#define SM_FLOATS  (MB_F + CR_F + 2*VBUF_F + EXP_F + 2*W_F + 16)
#define SMEM_BYTES (SM_FLOATS*4)

__device__ float g_eff[19];   // collapsed h->r conv weights (18) + bias

// ---------------- prep: collapse h_w/h_b/r_w into 2x3x3 eff conv ----------------
__global__ void vin_prep(const float* __restrict__ h_w,
                         const float* __restrict__ h_b,
                         const float* __restrict__ r_w) {
    int t = threadIdx.x;
    if (t < 18) {
        float s = 0.f;
        for (int c = 0; c < 150; ++c) s += r_w[c] * h_w[c*18 + t];
        g_eff[t] = s;
    } else if (t == 18) {
        float s = 0.f;
        for (int c = 0; c < 150; ++c) s += r_w[c] * h_b[c];
        g_eff[18] = s;
    }
}

// ---------------- f32x2 / PTX helpers ----------------
__device__ __forceinline__ unsigned long long dup2(float x) {
    unsigned long long d;
    asm("mov.b64 %0, {%1, %1};" : "=l"(d) : "f"(x));
    return d;
}
__device__ __forceinline__ unsigned long long fma2(unsigned long long a,
                                                   unsigned long long b,
                                                   unsigned long long c) {
    unsigned long long d;
    asm("fma.rn.f32x2 %0, %1, %2, %3;" : "=l"(d) : "l"(a), "l"(b), "l"(c));
    return d;
}
__device__ __forceinline__ float2 u2f(unsigned long long u) {
    float2 f;
    asm("mov.b64 {%0, %1}, %2;" : "=f"(f.x), "=f"(f.y) : "l"(u));
    return f;
}
__device__ __forceinline__ uint32_t smem_u32(const void* p) {
    uint32_t a;
    asm("{ .reg .u64 t; cvta.to.shared.u64 t, %1; cvt.u32.u64 %0, t; }"
        : "=r"(a) : "l"(p));
    return a;
}
__device__ __forceinline__ uint32_t mapa_rank(uint32_t addr, uint32_t rank) {
    uint32_t r;
    asm("mapa.shared::cluster.u32 %0, %1, %2;" : "=r"(r) : "r"(addr), "r"(rank));
    return r;
}
__device__ __forceinline__ float dsmem_ld(const float* p, uint32_t rank) {
    uint32_t a = smem_u32(p), r;
    asm("mapa.shared::cluster.u32 %0, %1, %2;" : "=r"(r) : "r"(a), "r"(rank));
    float v;
    asm volatile("ld.shared::cluster.f32 %0, [%1];" : "=f"(v) : "r"(r));
    return v;
}
__device__ __forceinline__ void mbar_init(uint32_t addr, uint32_t cnt) {
    asm volatile("mbarrier.init.shared.b64 [%0], %1;" :: "r"(addr), "r"(cnt) : "memory");
}
__device__ __forceinline__ void mbar_arrive_remote(uint32_t local_addr, uint32_t rank) {
    uint32_t raddr = mapa_rank(local_addr, rank);
    asm volatile("mbarrier.arrive.release.cluster.shared::cluster.b64 _, [%0];"
                 :: "r"(raddr) : "memory");
}
__device__ __forceinline__ void mbar_wait(uint32_t addr, uint32_t parity) {
    uint32_t done;
    do {
        asm volatile(
            "{ .reg .pred p;\n"
            "  mbarrier.try_wait.parity.acquire.cluster.shared::cta.b64 p, [%1], %2;\n"
            "  selp.b32 %0, 1, 0, p; }\n"
            : "=r"(done) : "r"(addr), "r"(parity) : "memory");
    } while (!done);
}
#define CLUSTER_SYNC() do { \
    asm volatile("barrier.cluster.arrive.aligned;" ::: "memory"); \
    asm volatile("barrier.cluster.wait.aligned;"   ::: "memory"); \
} while (0)

extern __shared__ float smem[];

// ---------------- main: 8-CTA cluster, 512 thr/CTA, 4 px/thread ----------------
__global__ void __launch_bounds__(NTHR, 2) __cluster_dims__(NCTA, 1, 1)
vin_main(const float* __restrict__ input_view,
         const int*   __restrict__ coords,
         const float* __restrict__ q_w,
         const float* __restrict__ w,
         const float* __restrict__ fc_w,
         float*       __restrict__ out)
{
    ulonglong2* crp = (ulonglong2*)(smem + MB_F);
    float* buf0 = smem + MB_F + CR_F;
    float* buf1 = buf0 + VBUF_F;
    float* exp_ = buf1 + VBUF_F;   // exp_top[par]=exp_+par*S ; exp_bot[par]=exp_+(2+par)*S
    float* wq_s = exp_ + EXP_F;
    float* wv_s = wq_s + W_F;
    float* qfin = wv_s + W_F;

    const int tid  = threadIdx.x;
    const int wid  = tid >> 5;
    const int lid  = tid & 31;
    const int img  = blockIdx.x >> 3;
    const int rank = blockIdx.x & 7;
    const int r0   = rank * RPC;

    const uint32_t mb_base = smem_u32(smem);

    // zero v buffers + exports + weights + qfin
    for (int i = tid; i < 2*VBUF_F + EXP_F + 2*W_F + 16; i += NTHR) buf0[i] = 0.f;
    if (tid == 0) {
        mbar_init(mb_base + 0,  1);   // top, slot 0
        mbar_init(mb_base + 8,  1);   // top, slot 1
        mbar_init(mb_base + 16, 1);   // bot, slot 0
        mbar_init(mb_base + 24, 1);   // bot, slot 1
    }
    __syncthreads();
    if (tid < 90) {
        int c = tid/9, t9 = tid%9, cp = c>>1, half = c&1;
        wq_s[(cp*10 + t9)*2 + half] = q_w[c*9 + t9];
        wv_s[(cp*10 + t9)*2 + half] = w  [c*9 + t9];
    }
    __syncthreads();
    CLUSTER_SYNC();   // mbar init visible cluster-wide before any remote arrive

    // ---- stage A: r rows [r0-1, r0+16] into buf1 (temp) ----
    {
        float e[19];
        #pragma unroll
        for (int i = 0; i < 19; ++i) e[i] = g_eff[i];
        const float* inb = input_view + (size_t)img * 2 * HS * HS;
        for (int idx = tid; idx < VROWS*HS; idx += NTHR) {
            int j = idx >> 7, x = idx & 127;
            int gy = r0 - 1 + j;
            float acc = 0.f;
            if ((unsigned)gy < (unsigned)HS) {
                acc = e[18];
                #pragma unroll
                for (int ch = 0; ch < 2; ++ch) {
                    const float* ip = inb + ch*HS*HS;
                    #pragma unroll
                    for (int ky = 0; ky < 3; ++ky) {
                        int yy = gy + ky - 1;
                        if ((unsigned)yy < (unsigned)HS) {
                            #pragma unroll
                            for (int kx = 0; kx < 3; ++kx) {
                                int xx = x + kx - 1;
                                if ((unsigned)xx < (unsigned)HS)
                                    acc += ip[yy*HS + xx] * e[ch*9 + ky*3 + kx];
                            }
                        }
                    }
                }
            }
            buf1[j*S + x + 1] = acc;
        }
    }
    __syncthreads();

    const int y  = tid >> 5;          // owned row 0..15 (one row per warp)
    const int x0 = (tid & 31) << 2;   // 0..124, 4 px per thread

    // ---- stage B: cr = conv(r, q_w), ull2 per (pp, cp, tid) ----
    {
        unsigned long long rd[3][6];
        #pragma unroll
        for (int rr = 0; rr < 3; ++rr) {
            const float* rowp = buf1 + (y+rr)*S + x0;   // idx x0..x0+5 = cols x0-1..x0+4
            float4 a = *(const float4*)rowp;
            float e4 = rowp[4], e5 = rowp[5];
            rd[rr][0]=dup2(a.x); rd[rr][1]=dup2(a.y); rd[rr][2]=dup2(a.z);
            rd[rr][3]=dup2(a.w); rd[rr][4]=dup2(e4);  rd[rr][5]=dup2(e5);
        }
        #pragma unroll
        for (int cp = 0; cp < 5; ++cp) {
            const ulonglong2* wp = (const ulonglong2*)(wq_s + cp*20);
            ulonglong2 w01 = wp[0], w23 = wp[1], w45 = wp[2], w67 = wp[3];
            unsigned long long W8 = *(const unsigned long long*)(wq_s + cp*20 + 16);
            unsigned long long acc[4];
            #pragma unroll
            for (int px = 0; px < 4; ++px) {
                unsigned long long a = fma2(rd[0][px],   w01.x, 0ull);
                // fma with 0 accumulator: use mul-equivalent via fma2(a,b,0)
                a = fma2(rd[0][px+1], w01.y, a);
                a = fma2(rd[0][px+2], w23.x, a);
                a = fma2(rd[1][px],   w23.y, a);
                a = fma2(rd[1][px+1], w45.x, a);
                a = fma2(rd[1][px+2], w45.y, a);
                a = fma2(rd[2][px],   w67.x, a);
                a = fma2(rd[2][px+1], w67.y, a);
                a = fma2(rd[2][px+2], W8,    a);
                acc[px] = a;
            }
            crp[(0*5 + cp)*NTHR + tid] = make_ulonglong2(acc[0], acc[1]);
            crp[(1*5 + cp)*NTHR + tid] = make_ulonglong2(acc[2], acc[3]);
        }
    }
    __syncthreads();
    for (int i = tid; i < VBUF_F; i += NTHR) buf1[i] = 0.f;
    __syncthreads();

    // ---- 40 sweeps; CTA barrier + edge-warp p2p cluster mbarriers ----
    #pragma unroll 1
    for (int it = 0; it < KITER; ++it) {
        const float* vc = (it & 1) ? buf1 : buf0;
        float*       vn = (it & 1) ? buf0 : buf1;
        const int b_out = it & 1;

        // edge warps: wait for neighbor's export of it-1, pull into vc halo row
        if (it > 0) {
            const int b_in = (it - 1) & 1;
            const uint32_t par = (uint32_t)(((it - 1) >> 1) & 1);
            if (wid == 0) {
                if (rank > 0) {
                    mbar_wait(mb_base + b_in*8, par);
                    #pragma unroll
                    for (int j = 0; j < 4; ++j) {
                        int xx = lid*4 + j;
                        ((float*)vc)[0*S + 1 + xx] =
                            dsmem_ld(exp_ + (2 + b_in)*S + 1 + xx, rank - 1);
                    }
                }
                __syncwarp();
            } else if (wid == 15) {
                if (rank < NCTA-1) {
                    mbar_wait(mb_base + 16 + b_in*8, par);
                    #pragma unroll
                    for (int j = 0; j < 4; ++j) {
                        int xx = lid*4 + j;
                        ((float*)vc)[(RPC+1)*S + 1 + xx] =
                            dsmem_ld(exp_ + b_in*S + 1 + xx, rank + 1);
                    }
                }
                __syncwarp();
            }
        }

        unsigned long long vd[3][6];
        #pragma unroll
        for (int rr = 0; rr < 3; ++rr) {
            const float* rowp = vc + (y+rr)*S + x0;
            float4 a = *(const float4*)rowp;
            float e4 = rowp[4], e5 = rowp[5];
            vd[rr][0]=dup2(a.x); vd[rr][1]=dup2(a.y); vd[rr][2]=dup2(a.z);
            vd[rr][3]=dup2(a.w); vd[rr][4]=dup2(e4);  vd[rr][5]=dup2(e5);
        }

        float vmx[4], vmy[4];
        #pragma unroll
        for (int cp = 0; cp < 5; ++cp) {
            const ulonglong2* wp = (const ulonglong2*)(wv_s + cp*20);
            ulonglong2 w01 = wp[0], w23 = wp[1], w45 = wp[2], w67 = wp[3];
            unsigned long long W8 = *(const unsigned long long*)(wv_s + cp*20 + 16);
            ulonglong2 c01 = crp[(0*5 + cp)*NTHR + tid];
            ulonglong2 c23 = crp[(1*5 + cp)*NTHR + tid];
            unsigned long long acc[4] = {c01.x, c01.y, c23.x, c23.y};
            #pragma unroll
            for (int px = 0; px < 4; ++px) {
                unsigned long long a = acc[px];
                a = fma2(vd[0][px],   w01.x, a);
                a = fma2(vd[0][px+1], w01.y, a);
                a = fma2(vd[0][px+2], w23.x, a);
                a = fma2(vd[1][px],   w23.y, a);
                a = fma2(vd[1][px+1], w45.x, a);
                a = fma2(vd[1][px+2], w45.y, a);
                a = fma2(vd[2][px],   w67.x, a);
                a = fma2(vd[2][px+1], w67.y, a);
                a = fma2(vd[2][px+2], W8,    a);
                float2 aa = u2f(a);
                if (cp == 0) { vmx[px] = aa.x;                 vmy[px] = aa.y; }
                else         { vmx[px] = fmaxf(vmx[px], aa.x); vmy[px] = fmaxf(vmy[px], aa.y); }
            }
        }
        float* vo = vn + (y+1)*S + x0 + 1;
        float res[4];
        #pragma unroll
        for (int px = 0; px < 4; ++px) { res[px] = fmaxf(vmx[px], vmy[px]); vo[px] = res[px]; }

        // edge-row exports into parity slots
        if (y == 0) {
            if (rank > 0) {
                float* e = exp_ + b_out*S + x0 + 1;
                #pragma unroll
                for (int px = 0; px < 4; ++px) e[px] = res[px];
            }
        } else if (y == 15) {
            if (rank < NCTA-1) {
                float* e = exp_ + (2 + b_out)*S + x0 + 1;
                #pragma unroll
                for (int px = 0; px < 4; ++px) e[px] = res[px];
            }
        }

        __syncthreads();   // vn + exports complete CTA-wide

        // signal neighbors: my iteration-it export is ready
        if (tid == 0) {
            if (rank > 0)       mbar_arrive_remote(mb_base + 16 + b_out*8, rank - 1); // their mb_bot
        } else if (tid == NTHR-1) {
            if (rank < NCTA-1)  mbar_arrive_remote(mb_base + b_out*8,      rank + 1); // their mb_top
        }
    }

    // ---- refresh buf0 halo for readout (final v = buf0, exported at it=39) ----
    {
        const int b = (KITER - 1) & 1;                            // 1
        const uint32_t par = (uint32_t)(((KITER - 1) >> 1) & 1);  // 1
        if (wid == 0) {
            if (rank > 0) {
                mbar_wait(mb_base + b*8, par);
                #pragma unroll
                for (int j = 0; j < 4; ++j) {
                    int xx = lid*4 + j;
                    buf0[0*S + 1 + xx] = dsmem_ld(exp_ + (2 + b)*S + 1 + xx, rank - 1);
                }
            }
        } else if (wid == 15) {
            if (rank < NCTA-1) {
                mbar_wait(mb_base + 16 + b*8, par);
                #pragma unroll
                for (int j = 0; j < 4; ++j) {
                    int xx = lid*4 + j;
                    buf0[(RPC+1)*S + 1 + xx] = dsmem_ld(exp_ + b*S + 1 + xx, rank + 1);
                }
            }
        }
    }
    __syncthreads();

    // ---- readout ----
    const int sx = coords[img*4 + 0];
    const int sy = coords[img*4 + 1];
    if ((sx >> 4) == rank) {
        const float* vf = buf0;
        const int yl = sx & 15;
        if (tid < 10) {
            int tt = yl*32 + (sy >> 2), slot = sy & 3;
            int cp = tid >> 1, half = tid & 1;
            ulonglong2 ce = crp[((slot >> 1)*5 + cp)*NTHR + tt];
            float2 crv = u2f((slot & 1) ? ce.y : ce.x);
            float acc = half ? crv.y : crv.x;
            #pragma unroll
            for (int rr = 0; rr < 3; ++rr)
                #pragma unroll
                for (int cc = 0; cc < 3; ++cc)
                    acc += w[tid*9 + rr*3 + cc] * vf[(yl + rr)*S + sy + cc];
            qfin[tid] = acc;
        }
        __syncthreads();
        if (tid < 5) {
            float s = 0.f;
            #pragma unroll
            for (int c = 0; c < 10; ++c) s += qfin[c] * fc_w[tid*10 + c];
            out[img*5 + tid] = s;
        }
    }

    // no CTA may exit while a neighbor's remote op targeting it can be in flight
    CLUSTER_SYNC();
}

extern "C" void kernel_launch(void* const* d_in, const int* in_sizes, int n_in,
                              void* d_out, int out_size) {
    const float* input_view = (const float*)d_in[0];
    const int*   coords     = (const int*)  d_in[1];
    const float* h_w        = (const float*)d_in[2];
    const float* h_b        = (const float*)d_in[3];
    const float* r_w        = (const float*)d_in[4];
    const float* q_w        = (const float*)d_in[5];
    const float* w          = (const float*)d_in[6];
    const float* fc_w       = (const float*)d_in[7];
    float* out = (float*)d_out;

    (void)in_sizes; (void)n_in; (void)out_size;

    vin_prep<<<1, 32>>>(h_w, h_b, r_w);

    cudaFuncSetAttribute(vin_main, cudaFuncAttributeMaxDynamicSharedMemorySize, SMEM_BYTES);
    vin_main<<<NIMG*NCTA, NTHR, SMEM_BYTES>>>(input_view, coords, q_w, w, fc_w, out);
}

// round 13
// speedup vs baseline: 1.2026x; 1.1438x over previous
#include <cuda_runtime.h>
#include <cstdint>

#define HS    128
#define KITER 40
#define NIMG  256
#define RPC   16            // rows per CTA
#define NCTA  8             // cluster size (8 * 16 = 128 rows)
#define S     132           // padded row stride (floats)
#define VROWS 18            // RPC + 2 halo rows
#define NTHR  256

#define MB_F       8                   // 4 mbarriers (u64) = 32 B
#define CR_F       (5*8*NTHR*2)        // cr: 20480 floats (80 KB)
#define VBUF_F     (VROWS*S)           // 2376 floats
#define EXP_F      (4*S)               // exp_top[2 par] + exp_bot[2 par]
#define SM_FLOATS  (MB_F + CR_F + 2*VBUF_F + EXP_F + 16)
#define SMEM_BYTES (SM_FLOATS*4)

__device__ float g_eff[19];                 // collapsed h->r conv weights (18) + bias
__device__ unsigned long long g_wpack[90];  // staging: [0..44]=q_w pairs, [45..89]=w pairs
__constant__ unsigned long long c_wq[45];   // (q_w[2cp][t], q_w[2cp+1][t]) at [cp*9+t]
__constant__ unsigned long long c_wv[45];   // (w  [2cp][t], w  [2cp+1][t]) at [cp*9+t]

// ---------------- prep: collapse h->r conv + pack weight channel-pairs ----------------
__global__ void vin_prep(const float* __restrict__ h_w,
                         const float* __restrict__ h_b,
                         const float* __restrict__ r_w,
                         const float* __restrict__ q_w,
                         const float* __restrict__ w) {
    int t = threadIdx.x;
    if (t < 18) {
        float s = 0.f;
        for (int c = 0; c < 150; ++c) s += r_w[c] * h_w[c*18 + t];
        g_eff[t] = s;
    } else if (t == 18) {
        float s = 0.f;
        for (int c = 0; c < 150; ++c) s += r_w[c] * h_b[c];
        g_eff[18] = s;
    }
    if (t < 45) {
        int cp = t / 9, t9 = t % 9;
        float lo = q_w[(2*cp)*9 + t9],  hi = q_w[(2*cp+1)*9 + t9];
        unsigned long long u;
        asm("mov.b64 %0, {%1, %2};" : "=l"(u) : "f"(lo), "f"(hi));
        g_wpack[t] = u;
        lo = w[(2*cp)*9 + t9];  hi = w[(2*cp+1)*9 + t9];
        asm("mov.b64 %0, {%1, %2};" : "=l"(u) : "f"(lo), "f"(hi));
        g_wpack[45 + t] = u;
    }
}

// ---------------- f32x2 / PTX helpers ----------------
__device__ __forceinline__ unsigned long long dup2(float x) {
    unsigned long long d;
    asm("mov.b64 %0, {%1, %1};" : "=l"(d) : "f"(x));
    return d;
}
__device__ __forceinline__ unsigned long long fma2(unsigned long long a,
                                                   unsigned long long b,
                                                   unsigned long long c) {
    unsigned long long d;
    asm("fma.rn.f32x2 %0, %1, %2, %3;" : "=l"(d) : "l"(a), "l"(b), "l"(c));
    return d;
}
__device__ __forceinline__ unsigned long long mul2(unsigned long long a,
                                                   unsigned long long b) {
    unsigned long long d;
    asm("mul.rn.f32x2 %0, %1, %2;" : "=l"(d) : "l"(a), "l"(b));
    return d;
}
__device__ __forceinline__ float2 u2f(unsigned long long u) {
    float2 f;
    asm("mov.b64 {%0, %1}, %2;" : "=f"(f.x), "=f"(f.y) : "l"(u));
    return f;
}
__device__ __forceinline__ uint32_t smem_u32(const void* p) {
    uint32_t a;
    asm("{ .reg .u64 t; cvta.to.shared.u64 t, %1; cvt.u32.u64 %0, t; }"
        : "=r"(a) : "l"(p));
    return a;
}
__device__ __forceinline__ uint32_t mapa_rank(uint32_t addr, uint32_t rank) {
    uint32_t r;
    asm("mapa.shared::cluster.u32 %0, %1, %2;" : "=r"(r) : "r"(addr), "r"(rank));
    return r;
}
__device__ __forceinline__ float dsmem_ld(const float* p, uint32_t rank) {
    uint32_t a = smem_u32(p), r;
    asm("mapa.shared::cluster.u32 %0, %1, %2;" : "=r"(r) : "r"(a), "r"(rank));
    float v;
    asm volatile("ld.shared::cluster.f32 %0, [%1];" : "=f"(v) : "r"(r));
    return v;
}
__device__ __forceinline__ void mbar_init(uint32_t addr, uint32_t cnt) {
    asm volatile("mbarrier.init.shared.b64 [%0], %1;" :: "r"(addr), "r"(cnt) : "memory");
}
__device__ __forceinline__ void mbar_arrive_remote(uint32_t local_addr, uint32_t rank) {
    uint32_t raddr = mapa_rank(local_addr, rank);
    asm volatile("mbarrier.arrive.release.cluster.shared::cluster.b64 _, [%0];"
                 :: "r"(raddr) : "memory");
}
__device__ __forceinline__ void mbar_wait(uint32_t addr, uint32_t parity) {
    uint32_t done;
    do {
        asm volatile(
            "{ .reg .pred p;\n"
            "  mbarrier.try_wait.parity.acquire.cluster.shared::cta.b64 p, [%1], %2;\n"
            "  selp.b32 %0, 1, 0, p; }\n"
            : "=r"(done) : "r"(addr), "r"(parity) : "memory");
    } while (!done);
}
__device__ __forceinline__ void named_bar(int id, int nthr) {
    asm volatile("bar.sync %0, %1;" :: "r"(id), "r"(nthr) : "memory");
}
#define CLUSTER_SYNC() do { \
    asm volatile("barrier.cluster.arrive.aligned;" ::: "memory"); \
    asm volatile("barrier.cluster.wait.aligned;"   ::: "memory"); \
} while (0)

extern __shared__ float smem[];

// ---------------- main: 8-CTA cluster, p2p mbarriers + pairwise warp barriers ----------------
__global__ void __launch_bounds__(NTHR, 2) __cluster_dims__(NCTA, 1, 1)
vin_main(const float* __restrict__ input_view,
         const int*   __restrict__ coords,
         const float* __restrict__ w,
         const float* __restrict__ fc_w,
         float*       __restrict__ out)
{
    ulonglong2* crp = (ulonglong2*)(smem + MB_F);
    float* buf0 = smem + MB_F + CR_F;
    float* buf1 = buf0 + VBUF_F;
    float* exp_ = buf1 + VBUF_F;   // exp_top[par]=exp_+par*S ; exp_bot[par]=exp_+(2+par)*S
    float* qfin = exp_ + EXP_F;

    const int tid  = threadIdx.x;
    const int wid  = tid >> 5;
    const int lid  = tid & 31;
    const int img  = blockIdx.x >> 3;
    const int rank = blockIdx.x & 7;
    const int r0   = rank * RPC;

    const uint32_t mb_base = smem_u32(smem);

    for (int i = tid; i < 2*VBUF_F + EXP_F + 16; i += NTHR) buf0[i] = 0.f;
    if (tid == 0) {
        mbar_init(mb_base + 0,  1);   // top, slot 0
        mbar_init(mb_base + 8,  1);   // top, slot 1
        mbar_init(mb_base + 16, 1);   // bot, slot 0
        mbar_init(mb_base + 24, 1);   // bot, slot 1
    }
    __syncthreads();
    CLUSTER_SYNC();   // mbar init visible cluster-wide before any remote arrive

    // ---- stage A: r rows [r0-1, r0+16] into buf1 (temp) ----
    {
        float e[19];
        #pragma unroll
        for (int i = 0; i < 19; ++i) e[i] = g_eff[i];
        const float* inb = input_view + (size_t)img * 2 * HS * HS;
        for (int idx = tid; idx < VROWS*HS; idx += NTHR) {
            int j = idx >> 7, x = idx & 127;
            int gy = r0 - 1 + j;
            float acc = 0.f;
            if ((unsigned)gy < (unsigned)HS) {
                acc = e[18];
                #pragma unroll
                for (int ch = 0; ch < 2; ++ch) {
                    const float* ip = inb + ch*HS*HS;
                    #pragma unroll
                    for (int ky = 0; ky < 3; ++ky) {
                        int yy = gy + ky - 1;
                        if ((unsigned)yy < (unsigned)HS) {
                            #pragma unroll
                            for (int kx = 0; kx < 3; ++kx) {
                                int xx = x + kx - 1;
                                if ((unsigned)xx < (unsigned)HS)
                                    acc += ip[yy*HS + xx] * e[ch*9 + ky*3 + kx];
                            }
                        }
                    }
                }
            }
            buf1[j*S + x + 1] = acc;
        }
    }
    __syncthreads();

    const int y  = tid >> 4;          // owned row 0..15
    const int x0 = (tid & 15) << 3;   // 0..120

    // ---- stage B: cr = conv(r, q_w), paired ulonglong2 layout; weights from const ----
    {
        unsigned long long rd[3][10];
        #pragma unroll
        for (int rr = 0; rr < 3; ++rr) {
            const float4* p = (const float4*)(buf1 + (y+rr)*S + x0);
            float4 a = p[0], b4 = p[1], c4 = p[2];
            rd[rr][0]=dup2(a.x);  rd[rr][1]=dup2(a.y);  rd[rr][2]=dup2(a.z);  rd[rr][3]=dup2(a.w);
            rd[rr][4]=dup2(b4.x); rd[rr][5]=dup2(b4.y); rd[rr][6]=dup2(b4.z); rd[rr][7]=dup2(b4.w);
            rd[rr][8]=dup2(c4.x); rd[rr][9]=dup2(c4.y);
        }
        #pragma unroll
        for (int cp = 0; cp < 5; ++cp) {
            unsigned long long acc[8];
            #pragma unroll
            for (int px = 0; px < 8; ++px) {
                unsigned long long a = mul2(rd[0][px], c_wq[cp*9+0]);
                a = fma2(rd[0][px+1], c_wq[cp*9+1], a);
                a = fma2(rd[0][px+2], c_wq[cp*9+2], a);
                a = fma2(rd[1][px],   c_wq[cp*9+3], a);
                a = fma2(rd[1][px+1], c_wq[cp*9+4], a);
                a = fma2(rd[1][px+2], c_wq[cp*9+5], a);
                a = fma2(rd[2][px],   c_wq[cp*9+6], a);
                a = fma2(rd[2][px+1], c_wq[cp*9+7], a);
                a = fma2(rd[2][px+2], c_wq[cp*9+8], a);
                acc[px] = a;
            }
            #pragma unroll
            for (int pp = 0; pp < 4; ++pp)
                crp[(pp*5 + cp)*NTHR + tid] = make_ulonglong2(acc[2*pp], acc[2*pp+1]);
        }
    }
    __syncthreads();
    for (int i = tid; i < VBUF_F; i += NTHR) buf1[i] = 0.f;
    __syncthreads();

    // ---- 40 sweeps; pairwise warp barriers + edge-warp p2p cluster mbarriers ----
    #pragma unroll 1
    for (int it = 0; it < KITER; ++it) {
        const float* vc = (it & 1) ? buf1 : buf0;
        float*       vn = (it & 1) ? buf0 : buf1;
        const int b_out = it & 1;

        // edge warps: wait for neighbor's export of it-1, pull into vc halo row
        if (it > 0) {
            const int b_in = (it - 1) & 1;
            const uint32_t par = (uint32_t)(((it - 1) >> 1) & 1);
            if (wid == 0) {
                if (rank > 0) {
                    mbar_wait(mb_base + b_in*8, par);
                    #pragma unroll
                    for (int j = 0; j < 4; ++j) {
                        int xx = lid*4 + j;
                        ((float*)vc)[0*S + 1 + xx] =
                            dsmem_ld(exp_ + (2 + b_in)*S + 1 + xx, rank - 1);
                    }
                }
                __syncwarp();
            } else if (wid == 7) {
                if (rank < NCTA-1) {
                    mbar_wait(mb_base + 16 + b_in*8, par);
                    #pragma unroll
                    for (int j = 0; j < 4; ++j) {
                        int xx = lid*4 + j;
                        ((float*)vc)[(RPC+1)*S + 1 + xx] =
                            dsmem_ld(exp_ + b_in*S + 1 + xx, rank + 1);
                    }
                }
                __syncwarp();
            }
        }

        unsigned long long vd[3][10];
        #pragma unroll
        for (int rr = 0; rr < 3; ++rr) {
            const float4* p = (const float4*)(vc + (y+rr)*S + x0);
            float4 a = p[0], b4 = p[1], c4 = p[2];
            vd[rr][0]=dup2(a.x);  vd[rr][1]=dup2(a.y);  vd[rr][2]=dup2(a.z);  vd[rr][3]=dup2(a.w);
            vd[rr][4]=dup2(b4.x); vd[rr][5]=dup2(b4.y); vd[rr][6]=dup2(b4.z); vd[rr][7]=dup2(b4.w);
            vd[rr][8]=dup2(c4.x); vd[rr][9]=dup2(c4.y);
        }

        float vmx[8], vmy[8];
        #pragma unroll
        for (int cp = 0; cp < 5; ++cp) {
            ulonglong2 c01 = crp[(0*5 + cp)*NTHR + tid];
            ulonglong2 c23 = crp[(1*5 + cp)*NTHR + tid];
            ulonglong2 c45 = crp[(2*5 + cp)*NTHR + tid];
            ulonglong2 c67 = crp[(3*5 + cp)*NTHR + tid];
            unsigned long long acc[8] = {c01.x, c01.y, c23.x, c23.y,
                                         c45.x, c45.y, c67.x, c67.y};
            #pragma unroll
            for (int px = 0; px < 8; ++px) {
                unsigned long long a = acc[px];
                a = fma2(vd[0][px],   c_wv[cp*9+0], a);
                a = fma2(vd[0][px+1], c_wv[cp*9+1], a);
                a = fma2(vd[0][px+2], c_wv[cp*9+2], a);
                a = fma2(vd[1][px],   c_wv[cp*9+3], a);
                a = fma2(vd[1][px+1], c_wv[cp*9+4], a);
                a = fma2(vd[1][px+2], c_wv[cp*9+5], a);
                a = fma2(vd[2][px],   c_wv[cp*9+6], a);
                a = fma2(vd[2][px+1], c_wv[cp*9+7], a);
                a = fma2(vd[2][px+2], c_wv[cp*9+8], a);
                float2 aa = u2f(a);
                if (cp == 0) { vmx[px] = aa.x;                 vmy[px] = aa.y; }
                else         { vmx[px] = fmaxf(vmx[px], aa.x); vmy[px] = fmaxf(vmy[px], aa.y); }
            }
        }
        float* vo = vn + (y+1)*S + x0 + 1;
        float res[8];
        #pragma unroll
        for (int px = 0; px < 8; ++px) { res[px] = fmaxf(vmx[px], vmy[px]); vo[px] = res[px]; }

        // edge-row exports into parity slots
        if (y == 0) {
            if (rank > 0) {
                float* e = exp_ + b_out*S + x0 + 1;
                #pragma unroll
                for (int px = 0; px < 8; ++px) e[px] = res[px];
            }
        } else if (y == 15) {
            if (rank < NCTA-1) {
                float* e = exp_ + (2 + b_out)*S + x0 + 1;
                #pragma unroll
                for (int px = 0; px < 8; ++px) e[px] = res[px];
            }
        }

        // edge warps: signal neighbor (release-arrive after export)
        if (wid == 0) {
            __syncwarp();
            if (lid == 0 && rank > 0)
                mbar_arrive_remote(mb_base + 16 + b_out*8, rank - 1);  // their mb_bot
        } else if (wid == 7) {
            __syncwarp();
            if (lid == 0 && rank < NCTA-1)
                mbar_arrive_remote(mb_base + b_out*8, rank + 1);        // their mb_top
        }

        // pairwise warp barriers: id b joins warps b-1 and b (64 threads).
        if (wid & 1) {
            named_bar(wid, 64);
            if (wid < 7) named_bar(wid + 1, 64);
        } else {
            if (wid < 7) named_bar(wid + 1, 64);
            if (wid > 0) named_bar(wid, 64);
        }
    }

    // ---- refresh buf0 halo for readout (final v = buf0, exported at it=39) ----
    {
        const int b = (KITER - 1) & 1;                            // 1
        const uint32_t par = (uint32_t)(((KITER - 1) >> 1) & 1);  // 1
        if (wid == 0) {
            if (rank > 0) {
                mbar_wait(mb_base + b*8, par);
                #pragma unroll
                for (int j = 0; j < 4; ++j) {
                    int xx = lid*4 + j;
                    buf0[0*S + 1 + xx] = dsmem_ld(exp_ + (2 + b)*S + 1 + xx, rank - 1);
                }
            }
        } else if (wid == 7) {
            if (rank < NCTA-1) {
                mbar_wait(mb_base + 16 + b*8, par);
                #pragma unroll
                for (int j = 0; j < 4; ++j) {
                    int xx = lid*4 + j;
                    buf0[(RPC+1)*S + 1 + xx] = dsmem_ld(exp_ + b*S + 1 + xx, rank + 1);
                }
            }
        }
    }
    __syncthreads();

    // ---- readout ----
    const int sx = coords[img*4 + 0];
    const int sy = coords[img*4 + 1];
    if ((sx >> 4) == rank) {
        const float* vf = buf0;
        const int yl = sx & 15;
        if (tid < 10) {
            int tt = yl*16 + (sy >> 3), slot = sy & 7;
            int cp = tid >> 1, half = tid & 1;
            ulonglong2 ce = crp[((slot >> 1)*5 + cp)*NTHR + tt];
            float2 crv = u2f((slot & 1) ? ce.y : ce.x);
            float acc = half ? crv.y : crv.x;
            #pragma unroll
            for (int rr = 0; rr < 3; ++rr)
                #pragma unroll
                for (int cc = 0; cc < 3; ++cc)
                    acc += w[tid*9 + rr*3 + cc] * vf[(yl + rr)*S + sy + cc];
            qfin[tid] = acc;
        }
        __syncthreads();
        if (tid < 5) {
            float s = 0.f;
            #pragma unroll
            for (int c = 0; c < 10; ++c) s += qfin[c] * fc_w[tid*10 + c];
            out[img*5 + tid] = s;
        }
    }

    // no CTA may exit while a neighbor's remote op targeting it can be in flight
    CLUSTER_SYNC();
}

extern "C" void kernel_launch(void* const* d_in, const int* in_sizes, int n_in,
                              void* d_out, int out_size) {
    const float* input_view = (const float*)d_in[0];
    const int*   coords     = (const int*)  d_in[1];
    const float* h_w        = (const float*)d_in[2];
    const float* h_b        = (const float*)d_in[3];
    const float* r_w        = (const float*)d_in[4];
    const float* q_w        = (const float*)d_in[5];
    const float* w          = (const float*)d_in[6];
    const float* fc_w       = (const float*)d_in[7];
    float* out = (float*)d_out;

    (void)in_sizes; (void)n_in; (void)out_size;

    vin_prep<<<1, 64>>>(h_w, h_b, r_w, q_w, w);

    // stage packed weight pairs into constant memory (async D2D, graph-capturable)
    void* wpack_ptr = nullptr;
    cudaGetSymbolAddress(&wpack_ptr, g_wpack);
    cudaMemcpyToSymbolAsync(c_wq, wpack_ptr, 45*sizeof(unsigned long long), 0,
                            cudaMemcpyDeviceToDevice, 0);
    cudaMemcpyToSymbolAsync(c_wv, (char*)wpack_ptr + 45*sizeof(unsigned long long),
                            45*sizeof(unsigned long long), 0,
                            cudaMemcpyDeviceToDevice, 0);

    cudaFuncSetAttribute(vin_main, cudaFuncAttributeMaxDynamicSharedMemorySize, SMEM_BYTES);
    vin_main<<<NIMG*NCTA, NTHR, SMEM_BYTES>>>(input_view, coords, w, fc_w, out);
}